// round 15
// baseline (speedup 1.0000x reference)
#include <cuda_runtime.h>
#include <math.h>
#include <stdint.h>
#include <stddef.h>

#define T_   128
#define B_   64
#define D_   256
#define H_   512
#define R_   4
#define N_   128
#define W_   64
#define HR   768
#define NIF  471
#define NIFP 480
#define GRID_ 128
#define TPB_  512

__device__ __align__(16) float g_h[2][B_*H_];
__device__ __align__(16) float g_r[B_*R_*W_];
__device__ __align__(16) float g_if[B_*NIFP];
__device__ unsigned g_bar;
__device__ unsigned g_rdy;

__device__ __forceinline__ float sigm(float x) { return 1.f/(1.f+expf(-x)); }
__device__ __forceinline__ float oneplus(float v) {
    float sp = (v > 20.f) ? v : log1pf(expf(v));
    return 1.f + sp;
}
__device__ __forceinline__ void fma2(unsigned long long &d, unsigned long long a, unsigned long long b) {
    asm("fma.rn.f32x2 %0, %1, %2, %3;" : "=l"(d) : "l"(a), "l"(b), "l"(d));
}
__device__ __forceinline__ float f2sum(unsigned long long v) {
    float lo = __uint_as_float((unsigned)(v & 0xffffffffull));
    float hi = __uint_as_float((unsigned)(v >> 32));
    return lo + hi;
}
#define CP_CG(dst, src) asm volatile("cp.async.cg.shared.global [%0], [%1], 16;" :: "r"(dst), "l"(src))
#define CP_COMMIT()     asm volatile("cp.async.commit_group;")
#define CP_WAIT2()      asm volatile("cp.async.wait_group 2;")
#define CP_WAIT1()      asm volatile("cp.async.wait_group 1;")
#define CP_WAIT0()      asm volatile("cp.async.wait_group 0;")

__device__ __forceinline__ void gbar(unsigned &tgt) {
    __syncthreads();
    if (threadIdx.x == 0) {
        __threadfence();
        atomicAdd(&g_bar, 1u);
        unsigned v;
        do {
            asm volatile("ld.acquire.gpu.u32 %0, [%1];" : "=r"(v) : "l"(&g_bar) : "memory");
            if (v < tgt) __nanosleep(20);
        } while (v < tgt);
    }
    __syncthreads();
    tgt += GRID_;
}

__global__ void k_init() {
    int i = blockIdx.x*blockDim.x + threadIdx.x;
    int stride = gridDim.x*blockDim.x;
    for (int idx = i; idx < 2*B_*H_; idx += stride) ((float*)g_h)[idx] = 0.f;
    for (int idx = i; idx < B_*R_*W_; idx += stride) g_r[idx] = 0.f;
    if (i == 0) { g_bar = 0u; g_rdy = 0u; }
}

// smem layout (floats)
#define LNK 132
#define OFF_LINK 0                          // 128*132 = 16896
#define OFF_MEM  16896                      // 8192
#define OFF_RWN  (16896+8192)               // 512
#define OFF_RWT  (OFF_RWN+512)              // 512
#define OFF_U    (OFF_RWT+512)              // 128
#define OFF_P    (OFF_U+128)                // 128
#define OFF_WW   (OFF_P+128)                // 128
#define OFF_S    (OFF_WW+128)               // 256
#define OFF_NORM (OFF_S+256)                // 128
#define OFF_SCR  (OFF_NORM+128)
#define SCR_FLOATS 21504                    // gates: 4x4352 A + 4x1024 W
#define SM_FLOATS (OFF_SCR + SCR_FLOATS)
#define SM_BYTES  (SM_FLOATS*4)

__global__ void __launch_bounds__(TPB_, 1) k_dnc(
    const float* __restrict__ x, const float* __restrict__ M0,
    const float* __restrict__ W_ih, const float* __restrict__ b_ih,
    const float* __restrict__ W_hh, const float* __restrict__ b_hh,
    const float* __restrict__ Wrk, const float* __restrict__ brk,
    const float* __restrict__ Wrs, const float* __restrict__ brs,
    const float* __restrict__ Wwk, const float* __restrict__ bwk,
    const float* __restrict__ Wws, const float* __restrict__ bws,
    const float* __restrict__ We,  const float* __restrict__ be,
    const float* __restrict__ Wv,  const float* __restrict__ bv,
    const float* __restrict__ Wfg, const float* __restrict__ bfg,
    const float* __restrict__ Wag, const float* __restrict__ bag,
    const float* __restrict__ Wwg, const float* __restrict__ bwg,
    const float* __restrict__ Wrm, const float* __restrict__ brm,
    float* __restrict__ out)
{
    extern __shared__ float sm[];
    float* linkS  = sm + OFF_LINK;
    float* memS   = sm + OFF_MEM;
    float* rwoldN = sm + OFF_RWN;
    float* rwoldT = sm + OFF_RWT;
    float* uS     = sm + OFF_U;
    float* pPer   = sm + OFF_P;
    float* wwPer  = sm + OFF_WW;
    float* sS     = sm + OFF_S;
    float* normM  = sm + OFF_NORM;
    float* scr    = sm + OFF_SCR;
    // state scratch (aliases gates/iface scratch)
    float* rwnewS= scr;          // 512
    float* crS   = scr + 512;    // 512
    float* fwdS  = scr + 1024;   // 512
    float* bwdS  = scr + 1536;   // 512
    float* bwdP  = scr + 2048;   // 8192
    float* suS   = scr + 10240;  // 128
    float* aAl   = scr + 10368;  // 128
    float* cwS   = scr + 10496;  // 128
    float* normP = scr + 10624;  // 512
    float* rkS   = scr + 11136;  // 256
    float* wkS   = scr + 11392;  // 64
    float* erS   = scr + 11456;  // 64
    float* wvS   = scr + 11520;  // 64
    float* fgS   = scr + 11584;  // 4
    float* rsS   = scr + 11588;  // 4
    float* rmS   = scr + 11592;  // 12
    float* rknS  = scr + 11604;  // 4
    float* scal  = scr + 11608;  // 8
    float* red   = scr + 11616;  // 8
    float* gpart = scr;          // gates partials [16rows][64b][16ks] = 16384 (aliases A buffers)

    const int tid  = threadIdx.x;
    const int lane = tid & 31, wid = tid >> 5;
    const int bid  = blockIdx.x;
    const unsigned FULL = 0xffffffffu;
    unsigned tgt = GRID_;

    uint32_t smemU32;
    asm("{ .reg .u64 t0; cvta.to.shared.u64 t0, %1; cvt.u32.u64 %0, t0; }" : "=r"(smemU32) : "l"(sm));

    // ---- one-time smem init ----
    if (bid < 64) {
        for (int i = tid; i < N_*W_; i += TPB_) memS[i] = M0[i];
        for (int i = tid; i < N_*LNK; i += TPB_) linkS[i] = 0.f;
        if (tid < 512) { rwoldN[tid] = 0.f; rwoldT[tid] = 0.f; }
        if (tid < 128) { uS[tid] = 1e-6f; pPer[tid] = 0.f; wwPer[tid] = 0.f; }
    }
    if (tid < 256) sS[tid] = 0.f;
    __syncthreads();
    if (bid < 64 && tid < 128) {
        float ss = 0.f;
        for (int k = 0; k < 64; k++) { float v = memS[tid*64+k]; ss += v*v; }
        normM[tid] = sqrtf(ss);
    }
    __syncthreads();

    const int jbase = bid * 4;
    // gates decomposition: jg(2) x bg(16) x ks(16)
    const int jg = tid >> 8;
    const int bg = (tid >> 4) & 15;
    const int ks = tid & 15;

    for (int t = 0; t < T_; t++) {
        // ================= gates phase (all 128 blocks), 4-deep pipeline =================
        // chunk order: x(0-3), h(8-15), r(4-7)  -> r staged last, gated on g_rdy
        {
            const float* hprev = g_h[t & 1];
            float* aBs[4] = {scr, scr + 4352, scr + 8704, scr + 13056};
            float* wBs[4] = {scr + 17408, scr + 18432, scr + 19456, scr + 20480};

            auto gstage = [&](int c) {
                int cc = (c < 4) ? c : ((c < 12) ? c + 4 : c - 8);
                int pb = c & 3;
                int k0 = cc * 64;
                const float* src; size_t strd;
                if (k0 < 256)      { src = x + (size_t)t*B_*D_ + k0; strd = D_; }
                else if (k0 < 512) { src = g_r + (k0-256);           strd = 256; }
                else               { src = hprev + (k0-512);         strd = H_; }
                uint32_t aDst = smemU32 + (uint32_t)(OFF_SCR + pb*4352)*4u;
                int f0 = tid, f1 = tid + 512;
                CP_CG(aDst + (uint32_t)((f0>>4)*68 + (f0&15)*4)*4u, src + (size_t)(f0>>4)*strd + (f0&15)*4);
                CP_CG(aDst + (uint32_t)((f1>>4)*68 + (f1&15)*4)*4u, src + (size_t)(f1>>4)*strd + (f1&15)*4);
                if (tid < 256) {
                    int row = tid >> 4, k4 = tid & 15;
                    int c2 = row >> 2, g = row & 3;
                    int G = g*H_ + jbase + c2;
                    const float* wp = (k0 < 512) ? (W_ih + (size_t)G*512 + k0)
                                                 : (W_hh + (size_t)G*512 + (k0-512));
                    uint32_t wDst = smemU32 + (uint32_t)(OFF_SCR + 17408 + pb*1024 + row*64 + k4*4)*4u;
                    CP_CG(wDst, wp + k4*4);
                }
                CP_COMMIT();
            };

            gstage(0); gstage(1); gstage(2);
            unsigned long long acc[32];
            #pragma unroll
            for (int i = 0; i < 32; i++) acc[i] = 0ull;

            for (int c = 0; c < 16; c++) {
                if (c == 9 && tid == 0) {      // r-chunks staged from c=9 (c+3=12): need g_r(t)
                    unsigned tv = 64u * (unsigned)t, v;
                    do {
                        asm volatile("ld.acquire.gpu.u32 %0, [%1];" : "=r"(v) : "l"(&g_rdy) : "memory");
                        if (v < tv) __nanosleep(20);
                    } while (v < tv);
                }
                if (c <= 13)      { CP_WAIT2(); }
                else if (c == 14) { CP_WAIT1(); }
                else              { CP_WAIT0(); }
                __syncthreads();                 // buffer c visible; reads of (c+3)&3 done; g_rdy poll done
                if (c + 3 < 16) gstage(c + 3);
                int pb = c & 3;
                const float* aB = aBs[pb];
                const float* wB = wBs[pb];
                ulonglong2 A2[4];
                #pragma unroll
                for (int bi = 0; bi < 4; bi++)
                    A2[bi] = *(const ulonglong2*)(aB + (bg*4+bi)*68 + ks*4);
                #pragma unroll
                for (int r8 = 0; r8 < 8; r8++) {
                    ulonglong2 W2 = *(const ulonglong2*)(wB + (jg*8+r8)*64 + ks*4);
                    fma2(acc[0*8+r8], A2[0].x, W2.x); fma2(acc[0*8+r8], A2[0].y, W2.y);
                    fma2(acc[1*8+r8], A2[1].x, W2.x); fma2(acc[1*8+r8], A2[1].y, W2.y);
                    fma2(acc[2*8+r8], A2[2].x, W2.x); fma2(acc[2*8+r8], A2[2].y, W2.y);
                    fma2(acc[3*8+r8], A2[3].x, W2.x); fma2(acc[3*8+r8], A2[3].y, W2.y);
                }
            }
            __syncthreads();   // buffers free -> gpart alias safe
            #pragma unroll
            for (int bi = 0; bi < 4; bi++)
                #pragma unroll
                for (int r8 = 0; r8 < 8; r8++)
                    gpart[((jg*8+r8)*64 + bg*4+bi)*16 + ks] = f2sum(acc[bi*8+r8]);
            __syncthreads();
            float red0 = 0.f, red1 = 0.f;
            {
                const float* p0 = gpart + tid*16;
                const float* p1 = gpart + (tid+512)*16;
                #pragma unroll
                for (int q = 0; q < 16; q++) { red0 += p0[q]; red1 += p1[q]; }
            }
            __syncthreads();
            gpart[tid] = red0; gpart[tid+512] = red1;
            __syncthreads();
            if (tid < 256) {
                int c2 = tid >> 6, b3 = tid & 63;
                int j = jbase + c2;
                float gv[4];
                #pragma unroll
                for (int g = 0; g < 4; g++)
                    gv[g] = gpart[(c2*4+g)*64 + b3] + b_ih[g*H_+j] + b_hh[g*H_+j];
                float sold = sS[c2*64 + b3];
                float snew = sigm(gv[1])*sold + sigm(gv[0])*tanhf(gv[2]);
                float hnew = sigm(gv[3])*tanhf(snew);
                sS[c2*64 + b3] = snew;
                g_h[(t&1)^1][b3*H_ + j] = hnew;
                out[((size_t)t*B_ + b3)*HR + j] = hnew;
            }
        }
        gbar(tgt);   // barA: h visible

        // ================= iface phase (blocks 0..117, 4 cols), 3-deep pipeline =================
        if (bid < 118) {
            const float* hcur = g_h[(t&1)^1];
            int Cbase = bid * 4;
            float* hBs[3] = {scr, scr + 4352, scr + 8704};
            float* biasS  = scr + 13824;
            float* gpartI = scr + 13856;       // [256 out][16 ks]
            const int ibg = tid >> 4;          // 0..31 (2 batches)
            const int iks = tid & 15;

            auto istage = [&](int c) {
                int pb = c % 3;
                int k0 = c * 64;
                uint32_t aDst = smemU32 + (uint32_t)(OFF_SCR + pb*4352)*4u;
                int f0 = tid, f1 = tid + 512;
                CP_CG(aDst + (uint32_t)((f0>>4)*68 + (f0&15)*4)*4u, hcur + (size_t)(f0>>4)*H_ + k0 + (f0&15)*4);
                CP_CG(aDst + (uint32_t)((f1>>4)*68 + (f1&15)*4)*4u, hcur + (size_t)(f1>>4)*H_ + k0 + (f1&15)*4);
                if (tid < 64) {
                    int row = tid >> 4, k4 = tid & 15;
                    int C = Cbase + row;
                    const float* wp = Wws;     // dummy-valid for C >= NIF
                    if (C < 256)       { int w = C>>2, r = C&3; wp = Wrk + ((size_t)r*W_ + w)*H_; }
                    else if (C < 260)  wp = Wrs + (C-256)*H_;
                    else if (C < 272)  wp = Wrm + (C-260)*H_;
                    else if (C < 276)  wp = Wfg + (C-272)*H_;
                    else if (C < 340)  wp = Wwk + (C-276)*H_;
                    else if (C == 340) wp = Wws;
                    else if (C < 405)  wp = We + (C-341)*H_;
                    else if (C < 469)  wp = Wv + (C-405)*H_;
                    else if (C == 469) wp = Wag;
                    else if (C == 470) wp = Wwg;
                    uint32_t wDst = smemU32 + (uint32_t)(OFF_SCR + 13056 + pb*256 + row*64 + k4*4)*4u;
                    CP_CG(wDst, wp + k0 + k4*4);
                }
                CP_COMMIT();
            };

            if (tid < 4) {
                int C = Cbase + tid; float bb = 0.f;
                if (C < 256)       { int w = C>>2, r = C&3; bb = brk[r*W_ + w]; }
                else if (C < 260)  bb = brs[C-256];
                else if (C < 272)  bb = brm[C-260];
                else if (C < 276)  bb = bfg[C-272];
                else if (C < 340)  bb = bwk[C-276];
                else if (C == 340) bb = bws[0];
                else if (C < 405)  bb = be[C-341];
                else if (C < 469)  bb = bv[C-405];
                else if (C == 469) bb = bag[0];
                else if (C == 470) bb = bwg[0];
                biasS[tid] = bb;
            }
            istage(0); istage(1);
            unsigned long long acc[8];
            #pragma unroll
            for (int i = 0; i < 8; i++) acc[i] = 0ull;

            for (int c = 0; c < 8; c++) {
                if (c <= 6) { CP_WAIT1(); } else { CP_WAIT0(); }
                __syncthreads();
                if (c + 2 < 8) istage(c + 2);
                int pb = c % 3;
                const float* hB = hBs[pb];
                const float* wI = scr + 13056 + pb*256;
                ulonglong2 A0 = *(const ulonglong2*)(hB + (ibg*2+0)*68 + iks*4);
                ulonglong2 A1 = *(const ulonglong2*)(hB + (ibg*2+1)*68 + iks*4);
                #pragma unroll
                for (int cc = 0; cc < 4; cc++) {
                    ulonglong2 W2 = *(const ulonglong2*)(wI + cc*64 + iks*4);
                    fma2(acc[0*4+cc], A0.x, W2.x); fma2(acc[0*4+cc], A0.y, W2.y);
                    fma2(acc[1*4+cc], A1.x, W2.x); fma2(acc[1*4+cc], A1.y, W2.y);
                }
            }
            __syncthreads();
            #pragma unroll
            for (int bi = 0; bi < 2; bi++)
                #pragma unroll
                for (int cc = 0; cc < 4; cc++)
                    gpartI[(cc*64 + ibg*2+bi)*16 + iks] = f2sum(acc[bi*4+cc]);
            __syncthreads();
            if (tid < 256) {
                int cc = tid >> 6, b3 = tid & 63;
                int C = Cbase + cc;
                if (C < NIF) {
                    const float* p = gpartI + tid*16;
                    float s_ = 0.f;
                    #pragma unroll
                    for (int q = 0; q < 16; q++) s_ += p[q];
                    g_if[b3*NIFP + C] = s_ + biasS[cc];
                }
            }
        }
        gbar(tgt);   // barB: g_if visible

        // ================= state phase (blocks 0..63); blocks 64-127 go to gates(t+1) =================
        if (bid < 64) {
            const int b = bid;
            const float* ifr = g_if + b*NIFP;
            const int n4 = tid >> 2, r4 = tid & 3;

            if (tid < 256) { int w = tid >> 2, r = tid & 3; rkS[r*64 + w] = __ldcg(ifr + tid); }
            else if (tid < 320) { int i = tid-256; wkS[i] = __ldcg(ifr + 276 + i); }
            else if (tid < 384) { int i = tid-320; erS[i] = sigm(__ldcg(ifr + 341 + i)); }
            else if (tid < 448) { int i = tid-384; wvS[i] = sigm(__ldcg(ifr + 405 + i)); }
            else if (tid < 452) {
                int i = tid-448;
                fgS[i] = sigm(__ldcg(ifr + 272 + i));
                rsS[i] = oneplus(__ldcg(ifr + 256 + i));
                float m0 = __ldcg(ifr+260+i*3+0), m1 = __ldcg(ifr+260+i*3+1), m2 = __ldcg(ifr+260+i*3+2);
                float mx = fmaxf(m0, fmaxf(m1, m2));
                float e0 = expf(m0-mx), e1 = expf(m1-mx), e2 = expf(m2-mx);
                float si = e0+e1+e2;
                rmS[i*3+0]=e0/si; rmS[i*3+1]=e1/si; rmS[i*3+2]=e2/si;
            }
            else if (tid == 500) {
                scal[1] = oneplus(__ldcg(ifr + 340));
                scal[2] = sigm(__ldcg(ifr + 469));
                scal[3] = sigm(__ldcg(ifr + 470));
            }
            __syncthreads();

            if (wid == 0) {
                float v = wkS[lane]*wkS[lane] + wkS[lane+32]*wkS[lane+32];
                #pragma unroll
                for (int o = 16; o; o >>= 1) v += __shfl_xor_sync(FULL, v, o);
                if (lane == 0) scal[0] = sqrtf(v);
            }
            if (wid >= 1 && wid <= 4) {
                int r = wid - 1;
                float a0 = rkS[r*64+lane], a1 = rkS[r*64+lane+32];
                float ss = a0*a0 + a1*a1;
                #pragma unroll
                for (int o = 16; o; o >>= 1) ss += __shfl_xor_sync(FULL, ss, o);
                if (lane == 0) rknS[r] = sqrtf(ss);
            }
            if (tid >= 160 && tid < 288) {
                int n = tid - 160;
                float4 rw4 = *(const float4*)(rwoldN + n*4);
                float psi = (1.f - fgS[0]*rw4.x)*(1.f - fgS[1]*rw4.y)
                          * (1.f - fgS[2]*rw4.z)*(1.f - fgS[3]*rw4.w);
                float uo = uS[n], wo = wwPer[n];
                float un = (uo + wo - uo*wo) * psi;
                suS[n] = un;
                uS[n] = un;
            }
            __syncthreads();

            if (wid == 0) {
                float v[4];
                #pragma unroll
                for (int s = 0; s < 4; s++) v[s] = suS[s*32 + lane];
                #pragma unroll
                for (int k = 2; k <= 128; k <<= 1) {
                    for (int j = k >> 1; j >= 32; j >>= 1) {
                        int js = j >> 5;
                        #pragma unroll
                        for (int s = 0; s < 4; s++) if (!(s & js)) {
                            int sp = s | js;
                            bool up = (((s*32 + lane) & k) == 0);
                            float lo = v[s], hi = v[sp];
                            float mn = fminf(lo, hi), mx = fmaxf(lo, hi);
                            v[s]  = up ? mn : mx;
                            v[sp] = up ? mx : mn;
                        }
                    }
                    for (int j = ((k>>1) > 16 ? 16 : (k>>1)); j >= 1; j >>= 1) {
                        #pragma unroll
                        for (int s = 0; s < 4; s++) {
                            bool up = (((s*32 + lane) & k) == 0);
                            float o = __shfl_xor_sync(FULL, v[s], j);
                            bool lower = ((lane & j) == 0);
                            v[s] = (up == lower) ? fminf(v[s], o) : fmaxf(v[s], o);
                        }
                    }
                }
                #pragma unroll
                for (int s = 0; s < 4; s++) suS[s*32 + lane] = v[s];
                __syncwarp();
                float w0 = suS[lane*4+0], w1 = suS[lane*4+1], w2 = suS[lane*4+2], w3 = suS[lane*4+3];
                float pl = w0*w1*w2*w3;
                float incl = pl;
                #pragma unroll
                for (int off = 1; off < 32; off <<= 1) {
                    float tv = __shfl_up_sync(FULL, incl, off);
                    if (lane >= off) incl *= tv;
                }
                float base = __shfl_up_sync(FULL, incl, 1);
                if (lane == 0) base = 1.f;
                float run = base;
                aAl[lane*4+0] = (1.f - w0)*run; run *= w0;
                aAl[lane*4+1] = (1.f - w1)*run; run *= w1;
                aAl[lane*4+2] = (1.f - w2)*run; run *= w2;
                aAl[lane*4+3] = (1.f - w3)*run;
            } else if (wid >= 8 && wid < 12) {
                int n = tid - 256;
                const float4* m4 = (const float4*)(memS + n*64);
                const float4* k4p = (const float4*)wkS;
                float d = 0.f;
                #pragma unroll
                for (int q = 0; q < 16; q++) {
                    float4 mv = m4[q], kv = k4p[q];
                    d += mv.x*kv.x + mv.y*kv.y + mv.z*kv.z + mv.w*kv.w;
                }
                cwS[n] = d / ((normM[n] + 1e-6f) * scal[0]) * scal[1];
            }
            __syncthreads();

            if (wid == 0) {
                float c0 = cwS[lane*4+0], c1 = cwS[lane*4+1], c2 = cwS[lane*4+2], c3 = cwS[lane*4+3];
                float mx = fmaxf(fmaxf(c0,c1), fmaxf(c2,c3));
                #pragma unroll
                for (int o = 16; o; o >>= 1) mx = fmaxf(mx, __shfl_xor_sync(FULL, mx, o));
                float e0 = expf(c0-mx), e1 = expf(c1-mx), e2 = expf(c2-mx), e3 = expf(c3-mx);
                float sme = e0+e1+e2+e3;
                #pragma unroll
                for (int o = 16; o; o >>= 1) sme += __shfl_xor_sync(FULL, sme, o);
                float inv = 1.f/sme;
                float ag = scal[2], wg = scal[3];
                float ww0 = wg*(ag*aAl[lane*4+0] + (1.f-ag)*e0*inv);
                float ww1 = wg*(ag*aAl[lane*4+1] + (1.f-ag)*e1*inv);
                float ww2 = wg*(ag*aAl[lane*4+2] + (1.f-ag)*e2*inv);
                float ww3 = wg*(ag*aAl[lane*4+3] + (1.f-ag)*e3*inv);
                wwPer[lane*4+0]=ww0; wwPer[lane*4+1]=ww1; wwPer[lane*4+2]=ww2; wwPer[lane*4+3]=ww3;
                float S = ww0+ww1+ww2+ww3;
                #pragma unroll
                for (int o = 16; o; o >>= 1) S += __shfl_xor_sync(FULL, S, o);
                float oms = 1.f - S;
                pPer[lane*4+0] = oms*pPer[lane*4+0] + ww0;
                pPer[lane*4+1] = oms*pPer[lane*4+1] + ww1;
                pPer[lane*4+2] = oms*pPer[lane*4+2] + ww2;
                pPer[lane*4+3] = oms*pPer[lane*4+3] + ww3;
            }
            __syncthreads();

            {
                int n = n4, q = r4;
                float wwn = wwPer[n];
                float4* m4 = (float4*)(memS + n*64 + q*16);
                const float4* wv4 = (const float4*)(wvS + q*16);
                const float4* er4 = (const float4*)(erS + q*16);
                float ss = 0.f;
                #pragma unroll
                for (int i = 0; i < 4; i++) {
                    float4 m = m4[i], wv = wv4[i], er = er4[i];
                    m.x += wwn*(wv.x - er.x); m.y += wwn*(wv.y - er.y);
                    m.z += wwn*(wv.z - er.z); m.w += wwn*(wv.w - er.w);
                    m4[i] = m;
                    ss += m.x*m.x + m.y*m.y + m.z*m.z + m.w*m.w;
                }
                normP[n*4 + q] = ss;
            }
            __syncthreads();

            {
                int n = n4, r = r4;
                float ssn = normP[n*4+0] + normP[n*4+1] + normP[n*4+2] + normP[n*4+3];
                float nrm = sqrtf(ssn);
                const float4* m4 = (const float4*)(memS + n*64);
                const float4* rk4 = (const float4*)(rkS + r*64);
                float c = 0.f;
                #pragma unroll
                for (int q = 0; q < 16; q++) {
                    float4 mv = m4[q], kv = rk4[q];
                    c += mv.x*kv.x + mv.y*kv.y + mv.z*kv.z + mv.w*kv.w;
                }
                crS[n*4+r] = c / (nrm + 1e-6f) / rknS[r] * rsS[r];
                if (r == 0) normM[n] = nrm;
            }
            __syncthreads();

            // P5: links update + bwd partials + fwd walk (fused)
            {
                float rj[4][4], pj[4], wwj[4], bw[4][4];
                #pragma unroll
                for (int q = 0; q < 4; q++) {
                    pj[q] = pPer[lane+32*q]; wwj[q] = wwPer[lane+32*q];
                    #pragma unroll
                    for (int r = 0; r < 4; r++) { rj[r][q] = rwoldT[r*128 + lane + 32*q]; bw[q][r] = 0.f; }
                }
                int i0 = wid * 8;
                for (int ii = 0; ii < 8; ii++) {
                    int i = i0 + ii;
                    float wi = wwPer[i];
                    float ri0 = rwoldN[i*4+0], ri1 = rwoldN[i*4+1], ri2 = rwoldN[i*4+2], ri3 = rwoldN[i*4+3];
                    float f0 = 0.f, f1 = 0.f, f2 = 0.f, f3 = 0.f;
                    #pragma unroll
                    for (int q = 0; q < 4; q++) {
                        int j = lane + 32*q;
                        float L = linkS[i*LNK + j];
                        L = (1.f - wi - wwj[q])*L + wi*pj[q];
                        if (i == j) L = 0.f;
                        linkS[i*LNK + j] = L;
                        bw[q][0] = fmaf(L, ri0, bw[q][0]);
                        bw[q][1] = fmaf(L, ri1, bw[q][1]);
                        bw[q][2] = fmaf(L, ri2, bw[q][2]);
                        bw[q][3] = fmaf(L, ri3, bw[q][3]);
                        f0 = fmaf(L, rj[0][q], f0);
                        f1 = fmaf(L, rj[1][q], f1);
                        f2 = fmaf(L, rj[2][q], f2);
                        f3 = fmaf(L, rj[3][q], f3);
                    }
                    #pragma unroll
                    for (int o = 16; o; o >>= 1) {
                        f0 += __shfl_xor_sync(FULL, f0, o);
                        f1 += __shfl_xor_sync(FULL, f1, o);
                        f2 += __shfl_xor_sync(FULL, f2, o);
                        f3 += __shfl_xor_sync(FULL, f3, o);
                    }
                    if (lane == 0) {
                        fwdS[i*4+0] = f0; fwdS[i*4+1] = f1;
                        fwdS[i*4+2] = f2; fwdS[i*4+3] = f3;
                    }
                }
                #pragma unroll
                for (int q = 0; q < 4; q++)
                    #pragma unroll
                    for (int r = 0; r < 4; r++)
                        bwdP[wid*512 + (lane+32*q)*4 + r] = bw[q][r];
            }
            __syncthreads();

            if (wid < 4) {
                int r = wid;
                float m = -1e30f;
                #pragma unroll
                for (int q = 0; q < 4; q++) m = fmaxf(m, crS[(lane + 32*q)*4 + r]);
                #pragma unroll
                for (int o = 16; o; o >>= 1) m = fmaxf(m, __shfl_xor_sync(FULL, m, o));
                float s_ = 0.f;
                #pragma unroll
                for (int q = 0; q < 4; q++) s_ += expf(crS[(lane + 32*q)*4 + r] - m);
                #pragma unroll
                for (int o = 16; o; o >>= 1) s_ += __shfl_xor_sync(FULL, s_, o);
                if (lane == 0) { red[r*2] = m; red[r*2+1] = s_; }
            } else if (wid < 8) {
                int t2 = (wid - 4)*32 + lane;
                #pragma unroll
                for (int q = 0; q < 4; q++) {
                    int jr = t2 + 128*q;
                    float acc2 = 0.f;
                    #pragma unroll
                    for (int w16 = 0; w16 < 16; w16++) acc2 += bwdP[w16*512 + jr];
                    bwdS[jr] = acc2;
                }
            }
            __syncthreads();

            if (tid < 128) {
                int n = tid;
                #pragma unroll
                for (int r = 0; r < 4; r++) {
                    float c = expf(crS[n*4+r] - red[r*2]) / red[r*2+1];
                    float v = rmS[r*3+0]*bwdS[n*4+r] + rmS[r*3+1]*c + rmS[r*3+2]*fwdS[n*4+r];
                    rwnewS[n*4+r] = v;
                }
            }
            __syncthreads();

            if (tid < 256) {
                int w = tid >> 2, r = tid & 3;
                float acc2 = 0.f;
                #pragma unroll 8
                for (int n = 0; n < 128; n++) acc2 = fmaf(memS[n*64+w], rwnewS[n*4+r], acc2);
                g_r[b*256 + w*4 + r] = acc2;
                out[((size_t)t*B_ + b)*HR + 512 + w*4 + r] = acc2;
            }
            rwoldN[tid] = rwnewS[tid];
            rwoldT[(tid & 3)*128 + (tid >> 2)] = rwnewS[tid];
            __syncthreads();
            if (tid == 0) { __threadfence(); atomicAdd(&g_rdy, 1u); }   // release g_r(t)
        }
        // no barC: gates(t+1) r-chunks gate on g_rdy
    }

    gbar(tgt);   // final: all out writes visible
    if (tid < 384) {
        int idx = bid*384 + tid;
        out[(size_t)T_*B_*HR + idx] = __ldcg(out + (size_t)(T_-1)*B_*HR + idx);
    }
}

extern "C" void kernel_launch(void* const* d_in, const int* in_sizes, int n_in,
                              void* d_out, int out_size) {
    const float* x    = (const float*)d_in[0];
    const float* M0   = (const float*)d_in[1];
    const float* W_ih = (const float*)d_in[2];
    const float* b_ih = (const float*)d_in[3];
    const float* W_hh = (const float*)d_in[4];
    const float* b_hh = (const float*)d_in[5];
    const float* Wrk  = (const float*)d_in[6];
    const float* brk  = (const float*)d_in[7];
    const float* Wrs  = (const float*)d_in[8];
    const float* brs  = (const float*)d_in[9];
    const float* Wwk  = (const float*)d_in[10];
    const float* bwk  = (const float*)d_in[11];
    const float* Wws  = (const float*)d_in[12];
    const float* bws  = (const float*)d_in[13];
    const float* We   = (const float*)d_in[14];
    const float* be   = (const float*)d_in[15];
    const float* Wv   = (const float*)d_in[16];
    const float* bv   = (const float*)d_in[17];
    const float* Wfg  = (const float*)d_in[18];
    const float* bfg  = (const float*)d_in[19];
    const float* Wag  = (const float*)d_in[20];
    const float* bag  = (const float*)d_in[21];
    const float* Wwg  = (const float*)d_in[22];
    const float* bwg  = (const float*)d_in[23];
    const float* Wrm  = (const float*)d_in[24];
    const float* brm  = (const float*)d_in[25];
    float* out = (float*)d_out;

    cudaFuncSetAttribute(k_dnc, cudaFuncAttributeMaxDynamicSharedMemorySize, SM_BYTES);

    k_init<<<128, 256>>>();
    k_dnc<<<GRID_, TPB_, SM_BYTES>>>(x, M0, W_ih, b_ih, W_hh, b_hh,
        Wrk, brk, Wrs, brs, Wwk, bwk, Wws, bws, We, be, Wv, bv,
        Wfg, bfg, Wag, bag, Wwg, bwg, Wrm, brm, out);
}

// round 16
// speedup vs baseline: 1.0299x; 1.0299x over previous
#include <cuda_runtime.h>
#include <math.h>
#include <stdint.h>
#include <stddef.h>

#define T_   128
#define B_   64
#define D_   256
#define H_   512
#define R_   4
#define N_   128
#define W_   64
#define HR   768
#define NIF  471
#define NIFP 480
#define GRID_ 128
#define TPB_  512

__device__ __align__(16) float g_h[2][B_*H_];
__device__ __align__(16) float g_r[B_*R_*W_];
__device__ __align__(16) float g_if[B_*NIFP];
__device__ unsigned g_bar;

__device__ __forceinline__ float sigm(float x) { return 1.f/(1.f+expf(-x)); }
__device__ __forceinline__ float oneplus(float v) {
    float sp = (v > 20.f) ? v : log1pf(expf(v));
    return 1.f + sp;
}
__device__ __forceinline__ void fma2(unsigned long long &d, unsigned long long a, unsigned long long b) {
    asm("fma.rn.f32x2 %0, %1, %2, %3;" : "=l"(d) : "l"(a), "l"(b), "l"(d));
}
__device__ __forceinline__ float f2sum(unsigned long long v) {
    float lo = __uint_as_float((unsigned)(v & 0xffffffffull));
    float hi = __uint_as_float((unsigned)(v >> 32));
    return lo + hi;
}
#define CP_CG(dst, src) asm volatile("cp.async.cg.shared.global [%0], [%1], 16;" :: "r"(dst), "l"(src))
#define CP_COMMIT()     asm volatile("cp.async.commit_group;")
#define CP_WAIT2()      asm volatile("cp.async.wait_group 2;")
#define CP_WAIT1()      asm volatile("cp.async.wait_group 1;")
#define CP_WAIT0()      asm volatile("cp.async.wait_group 0;")

__device__ __forceinline__ void gbar(unsigned &tgt) {
    __syncthreads();
    if (threadIdx.x == 0) {
        __threadfence();
        atomicAdd(&g_bar, 1u);
        unsigned v;
        do {
            asm volatile("ld.acquire.gpu.u32 %0, [%1];" : "=r"(v) : "l"(&g_bar) : "memory");
            if (v < tgt) __nanosleep(20);
        } while (v < tgt);
    }
    __syncthreads();
    tgt += GRID_;
}

__global__ void k_init() {
    int i = blockIdx.x*blockDim.x + threadIdx.x;
    int stride = gridDim.x*blockDim.x;
    for (int idx = i; idx < 2*B_*H_; idx += stride) ((float*)g_h)[idx] = 0.f;
    for (int idx = i; idx < B_*R_*W_; idx += stride) g_r[idx] = 0.f;
    if (i == 0) g_bar = 0u;
}

// smem layout (floats)
#define LNK 132
#define OFF_LINK 0                          // 128*132 = 16896
#define OFF_MEM  16896                      // 8192
#define OFF_RWN  (16896+8192)               // 512
#define OFF_RWT  (OFF_RWN+512)              // 512
#define OFF_U    (OFF_RWT+512)              // 128
#define OFF_P    (OFF_U+128)                // 128
#define OFF_WW   (OFF_P+128)                // 128
#define OFF_S    (OFF_WW+128)               // 256
#define OFF_NORM (OFF_S+256)                // 128
#define OFF_SCR  (OFF_NORM+128)
#define SCR_FLOATS 21504                    // gates: 4x4352 A + 4x1024 W
#define SM_FLOATS (OFF_SCR + SCR_FLOATS)
#define SM_BYTES  (SM_FLOATS*4)

__global__ void __launch_bounds__(TPB_, 1) k_dnc(
    const float* __restrict__ x, const float* __restrict__ M0,
    const float* __restrict__ W_ih, const float* __restrict__ b_ih,
    const float* __restrict__ W_hh, const float* __restrict__ b_hh,
    const float* __restrict__ Wrk, const float* __restrict__ brk,
    const float* __restrict__ Wrs, const float* __restrict__ brs,
    const float* __restrict__ Wwk, const float* __restrict__ bwk,
    const float* __restrict__ Wws, const float* __restrict__ bws,
    const float* __restrict__ We,  const float* __restrict__ be,
    const float* __restrict__ Wv,  const float* __restrict__ bv,
    const float* __restrict__ Wfg, const float* __restrict__ bfg,
    const float* __restrict__ Wag, const float* __restrict__ bag,
    const float* __restrict__ Wwg, const float* __restrict__ bwg,
    const float* __restrict__ Wrm, const float* __restrict__ brm,
    float* __restrict__ out)
{
    extern __shared__ float sm[];
    float* linkS  = sm + OFF_LINK;
    float* memS   = sm + OFF_MEM;
    float* rwoldN = sm + OFF_RWN;
    float* rwoldT = sm + OFF_RWT;
    float* uS     = sm + OFF_U;
    float* pPer   = sm + OFF_P;
    float* wwPer  = sm + OFF_WW;
    float* sS     = sm + OFF_S;
    float* normM  = sm + OFF_NORM;
    float* scr    = sm + OFF_SCR;
    // state scratch (aliases gates/iface scratch)
    float* rwnewS= scr;          // 512
    float* crS   = scr + 512;    // 512
    float* fwdS  = scr + 1024;   // 512
    float* bwdS  = scr + 1536;   // 512
    float* bwdP  = scr + 2048;   // 8192
    float* suS   = scr + 10240;  // 128
    float* aAl   = scr + 10368;  // 128
    float* cwS   = scr + 10496;  // 128
    float* normP = scr + 10624;  // 512
    float* rkS   = scr + 11136;  // 256
    float* wkS   = scr + 11392;  // 64
    float* erS   = scr + 11456;  // 64
    float* wvS   = scr + 11520;  // 64
    float* fgS   = scr + 11584;  // 4
    float* rsS   = scr + 11588;  // 4
    float* rmS   = scr + 11592;  // 12
    float* rknS  = scr + 11604;  // 4
    float* scal  = scr + 11608;  // 8
    float* red   = scr + 11616;  // 8
    float* gpart = scr;          // gates partials [1024 out][17] = 17408 (aliases A buffers)

    const int tid  = threadIdx.x;
    const int lane = tid & 31, wid = tid >> 5;
    const int bid  = blockIdx.x;
    const unsigned FULL = 0xffffffffu;
    unsigned tgt = GRID_;

    uint32_t smemU32;
    asm("{ .reg .u64 t0; cvta.to.shared.u64 t0, %1; cvt.u32.u64 %0, t0; }" : "=r"(smemU32) : "l"(sm));

    // ---- one-time smem init ----
    if (bid < 64) {
        for (int i = tid; i < N_*W_; i += TPB_) memS[i] = M0[i];
        for (int i = tid; i < N_*LNK; i += TPB_) linkS[i] = 0.f;
        if (tid < 512) { rwoldN[tid] = 0.f; rwoldT[tid] = 0.f; }
        if (tid < 128) { uS[tid] = 1e-6f; pPer[tid] = 0.f; wwPer[tid] = 0.f; }
    }
    if (tid < 256) sS[tid] = 0.f;
    __syncthreads();
    if (bid < 64 && tid < 128) {
        float ss = 0.f;
        for (int k = 0; k < 64; k++) { float v = memS[tid*64+k]; ss += v*v; }
        normM[tid] = sqrtf(ss);
    }
    __syncthreads();

    const int jbase = bid * 4;
    // gates decomposition: jg(2) x bg(16) x ks(16)
    const int jg = tid >> 8;
    const int bg = (tid >> 4) & 15;
    const int ks = tid & 15;

    for (int t = 0; t < T_; t++) {
        // ================= gates phase (all 128 blocks), 4-deep pipeline =================
        {
            const float* hprev = g_h[t & 1];
            float* aBs[4] = {scr, scr + 4352, scr + 8704, scr + 13056};
            float* wBs[4] = {scr + 17408, scr + 18432, scr + 19456, scr + 20480};

            auto gstage = [&](int cc) {
                int pb = cc & 3;
                int k0 = cc * 64;
                const float* src; size_t strd;
                if (k0 < 256)      { src = x + (size_t)t*B_*D_ + k0; strd = D_; }
                else if (k0 < 512) { src = g_r + (k0-256);           strd = 256; }
                else               { src = hprev + (k0-512);         strd = H_; }
                uint32_t aDst = smemU32 + (uint32_t)(OFF_SCR + pb*4352)*4u;
                int f0 = tid, f1 = tid + 512;
                CP_CG(aDst + (uint32_t)((f0>>4)*68 + (f0&15)*4)*4u, src + (size_t)(f0>>4)*strd + (f0&15)*4);
                CP_CG(aDst + (uint32_t)((f1>>4)*68 + (f1&15)*4)*4u, src + (size_t)(f1>>4)*strd + (f1&15)*4);
                if (tid < 256) {
                    int row = tid >> 4, k4 = tid & 15;
                    int c2 = row >> 2, g = row & 3;
                    int G = g*H_ + jbase + c2;
                    const float* wp = (k0 < 512) ? (W_ih + (size_t)G*512 + k0)
                                                 : (W_hh + (size_t)G*512 + (k0-512));
                    uint32_t wDst = smemU32 + (uint32_t)(OFF_SCR + 17408 + pb*1024 + row*64 + k4*4)*4u;
                    CP_CG(wDst, wp + k4*4);
                }
                CP_COMMIT();
            };

            gstage(0); gstage(1); gstage(2);
            unsigned long long acc[32];
            #pragma unroll
            for (int i = 0; i < 32; i++) acc[i] = 0ull;

            for (int c = 0; c < 16; c++) {
                if (c <= 13)      { CP_WAIT2(); }
                else if (c == 14) { CP_WAIT1(); }
                else              { CP_WAIT0(); }
                __syncthreads();                 // buffer c visible; reads of (c+3)&3 (iter c-1) done
                if (c + 3 < 16) gstage(c + 3);   // safe behind the sync
                int pb = c & 3;
                const float* aB = aBs[pb];
                const float* wB = wBs[pb];
                ulonglong2 A2[4];
                #pragma unroll
                for (int bi = 0; bi < 4; bi++)
                    A2[bi] = *(const ulonglong2*)(aB + (bg*4+bi)*68 + ks*4);
                #pragma unroll
                for (int r8 = 0; r8 < 8; r8++) {
                    ulonglong2 W2 = *(const ulonglong2*)(wB + (jg*8+r8)*64 + ks*4);
                    fma2(acc[0*8+r8], A2[0].x, W2.x); fma2(acc[0*8+r8], A2[0].y, W2.y);
                    fma2(acc[1*8+r8], A2[1].x, W2.x); fma2(acc[1*8+r8], A2[1].y, W2.y);
                    fma2(acc[2*8+r8], A2[2].x, W2.x); fma2(acc[2*8+r8], A2[2].y, W2.y);
                    fma2(acc[3*8+r8], A2[3].x, W2.x); fma2(acc[3*8+r8], A2[3].y, W2.y);
                }
            }
            __syncthreads();   // buffers free -> gpart alias safe
            #pragma unroll
            for (int bi = 0; bi < 4; bi++)
                #pragma unroll
                for (int r8 = 0; r8 < 8; r8++)
                    gpart[((jg*8+r8)*64 + bg*4+bi)*17 + ks] = f2sum(acc[bi*8+r8]);
            __syncthreads();
            float red0 = 0.f, red1 = 0.f;
            {
                const float* p0 = gpart + tid*17;
                const float* p1 = gpart + (tid+512)*17;
                #pragma unroll
                for (int q = 0; q < 16; q++) { red0 += p0[q]; red1 += p1[q]; }
            }
            __syncthreads();
            gpart[tid] = red0; gpart[tid+512] = red1;
            __syncthreads();
            if (tid < 256) {
                int c2 = tid >> 6, b3 = tid & 63;
                int j = jbase + c2;
                float gv[4];
                #pragma unroll
                for (int g = 0; g < 4; g++)
                    gv[g] = gpart[(c2*4+g)*64 + b3] + b_ih[g*H_+j] + b_hh[g*H_+j];
                float sold = sS[c2*64 + b3];
                float snew = sigm(gv[1])*sold + sigm(gv[0])*tanhf(gv[2]);
                float hnew = sigm(gv[3])*tanhf(snew);
                sS[c2*64 + b3] = snew;
                g_h[(t&1)^1][b3*H_ + j] = hnew;
                out[((size_t)t*B_ + b3)*HR + j] = hnew;
            }
        }
        gbar(tgt);   // barA: h visible

        // ================= iface phase (blocks 0..117, 4 cols), 3-deep pipeline =================
        if (bid < 118) {
            const float* hcur = g_h[(t&1)^1];
            int Cbase = bid * 4;
            float* hBs[3] = {scr, scr + 4352, scr + 8704};
            float* biasS  = scr + 13824;
            float* gpartI = scr + 13856;       // [256 out][17] = 4352
            const int ibg = tid >> 4;          // 0..31 (2 batches)
            const int iks = tid & 15;

            auto istage = [&](int c) {
                int pb = c % 3;
                int k0 = c * 64;
                uint32_t aDst = smemU32 + (uint32_t)(OFF_SCR + pb*4352)*4u;
                int f0 = tid, f1 = tid + 512;
                CP_CG(aDst + (uint32_t)((f0>>4)*68 + (f0&15)*4)*4u, hcur + (size_t)(f0>>4)*H_ + k0 + (f0&15)*4);
                CP_CG(aDst + (uint32_t)((f1>>4)*68 + (f1&15)*4)*4u, hcur + (size_t)(f1>>4)*H_ + k0 + (f1&15)*4);
                if (tid < 64) {
                    int row = tid >> 4, k4 = tid & 15;
                    int C = Cbase + row;
                    const float* wp = Wws;     // dummy-valid for C >= NIF
                    if (C < 256)       { int w = C>>2, r = C&3; wp = Wrk + ((size_t)r*W_ + w)*H_; }
                    else if (C < 260)  wp = Wrs + (C-256)*H_;
                    else if (C < 272)  wp = Wrm + (C-260)*H_;
                    else if (C < 276)  wp = Wfg + (C-272)*H_;
                    else if (C < 340)  wp = Wwk + (C-276)*H_;
                    else if (C == 340) wp = Wws;
                    else if (C < 405)  wp = We + (C-341)*H_;
                    else if (C < 469)  wp = Wv + (C-405)*H_;
                    else if (C == 469) wp = Wag;
                    else if (C == 470) wp = Wwg;
                    uint32_t wDst = smemU32 + (uint32_t)(OFF_SCR + 13056 + pb*256 + row*64 + k4*4)*4u;
                    CP_CG(wDst, wp + k0 + k4*4);
                }
                CP_COMMIT();
            };

            if (tid < 4) {
                int C = Cbase + tid; float bb = 0.f;
                if (C < 256)       { int w = C>>2, r = C&3; bb = brk[r*W_ + w]; }
                else if (C < 260)  bb = brs[C-256];
                else if (C < 272)  bb = brm[C-260];
                else if (C < 276)  bb = bfg[C-272];
                else if (C < 340)  bb = bwk[C-276];
                else if (C == 340) bb = bws[0];
                else if (C < 405)  bb = be[C-341];
                else if (C < 469)  bb = bv[C-405];
                else if (C == 469) bb = bag[0];
                else if (C == 470) bb = bwg[0];
                biasS[tid] = bb;
            }
            istage(0); istage(1);
            unsigned long long acc[8];
            #pragma unroll
            for (int i = 0; i < 8; i++) acc[i] = 0ull;

            for (int c = 0; c < 8; c++) {
                if (c <= 6) { CP_WAIT1(); } else { CP_WAIT0(); }
                __syncthreads();
                if (c + 2 < 8) istage(c + 2);
                int pb = c % 3;
                const float* hB = hBs[pb];
                const float* wI = scr + 13056 + pb*256;
                ulonglong2 A0 = *(const ulonglong2*)(hB + (ibg*2+0)*68 + iks*4);
                ulonglong2 A1 = *(const ulonglong2*)(hB + (ibg*2+1)*68 + iks*4);
                #pragma unroll
                for (int cc = 0; cc < 4; cc++) {
                    ulonglong2 W2 = *(const ulonglong2*)(wI + cc*64 + iks*4);
                    fma2(acc[0*4+cc], A0.x, W2.x); fma2(acc[0*4+cc], A0.y, W2.y);
                    fma2(acc[1*4+cc], A1.x, W2.x); fma2(acc[1*4+cc], A1.y, W2.y);
                }
            }
            __syncthreads();
            #pragma unroll
            for (int bi = 0; bi < 2; bi++)
                #pragma unroll
                for (int cc = 0; cc < 4; cc++)
                    gpartI[(cc*64 + ibg*2+bi)*17 + iks] = f2sum(acc[bi*4+cc]);
            __syncthreads();
            if (tid < 256) {
                int cc = tid >> 6, b3 = tid & 63;
                int C = Cbase + cc;
                if (C < NIF) {
                    const float* p = gpartI + tid*17;
                    float s_ = 0.f;
                    #pragma unroll
                    for (int q = 0; q < 16; q++) s_ += p[q];
                    g_if[b3*NIFP + C] = s_ + biasS[cc];
                }
            }
        }
        gbar(tgt);   // barB: g_if visible

        // ================= state phase (blocks 0..63) =================
        if (bid < 64) {
            const int b = bid;
            const float* ifr = g_if + b*NIFP;
            const int n4 = tid >> 2, r4 = tid & 3;

            if (tid < 256) { int w = tid >> 2, r = tid & 3; rkS[r*64 + w] = __ldcg(ifr + tid); }
            else if (tid < 320) { int i = tid-256; wkS[i] = __ldcg(ifr + 276 + i); }
            else if (tid < 384) { int i = tid-320; erS[i] = sigm(__ldcg(ifr + 341 + i)); }
            else if (tid < 448) { int i = tid-384; wvS[i] = sigm(__ldcg(ifr + 405 + i)); }
            else if (tid < 452) {
                int i = tid-448;
                fgS[i] = sigm(__ldcg(ifr + 272 + i));
                rsS[i] = oneplus(__ldcg(ifr + 256 + i));
                float m0 = __ldcg(ifr+260+i*3+0), m1 = __ldcg(ifr+260+i*3+1), m2 = __ldcg(ifr+260+i*3+2);
                float mx = fmaxf(m0, fmaxf(m1, m2));
                float e0 = expf(m0-mx), e1 = expf(m1-mx), e2 = expf(m2-mx);
                float si = e0+e1+e2;
                rmS[i*3+0]=e0/si; rmS[i*3+1]=e1/si; rmS[i*3+2]=e2/si;
            }
            else if (tid == 500) {
                scal[1] = oneplus(__ldcg(ifr + 340));
                scal[2] = sigm(__ldcg(ifr + 469));
                scal[3] = sigm(__ldcg(ifr + 470));
            }
            __syncthreads();

            if (wid == 0) {
                float v = wkS[lane]*wkS[lane] + wkS[lane+32]*wkS[lane+32];
                #pragma unroll
                for (int o = 16; o; o >>= 1) v += __shfl_xor_sync(FULL, v, o);
                if (lane == 0) scal[0] = sqrtf(v);
            }
            if (wid >= 1 && wid <= 4) {
                int r = wid - 1;
                float a0 = rkS[r*64+lane], a1 = rkS[r*64+lane+32];
                float ss = a0*a0 + a1*a1;
                #pragma unroll
                for (int o = 16; o; o >>= 1) ss += __shfl_xor_sync(FULL, ss, o);
                if (lane == 0) rknS[r] = sqrtf(ss);
            }
            if (tid >= 160 && tid < 288) {
                int n = tid - 160;
                float4 rw4 = *(const float4*)(rwoldN + n*4);
                float psi = (1.f - fgS[0]*rw4.x)*(1.f - fgS[1]*rw4.y)
                          * (1.f - fgS[2]*rw4.z)*(1.f - fgS[3]*rw4.w);
                float uo = uS[n], wo = wwPer[n];
                float un = (uo + wo - uo*wo) * psi;
                suS[n] = un;
                uS[n] = un;
            }
            __syncthreads();

            if (wid == 0) {
                float v[4];
                #pragma unroll
                for (int s = 0; s < 4; s++) v[s] = suS[s*32 + lane];
                #pragma unroll
                for (int k = 2; k <= 128; k <<= 1) {
                    for (int j = k >> 1; j >= 32; j >>= 1) {
                        int js = j >> 5;
                        #pragma unroll
                        for (int s = 0; s < 4; s++) if (!(s & js)) {
                            int sp = s | js;
                            bool up = (((s*32 + lane) & k) == 0);
                            float lo = v[s], hi = v[sp];
                            float mn = fminf(lo, hi), mx = fmaxf(lo, hi);
                            v[s]  = up ? mn : mx;
                            v[sp] = up ? mx : mn;
                        }
                    }
                    for (int j = ((k>>1) > 16 ? 16 : (k>>1)); j >= 1; j >>= 1) {
                        #pragma unroll
                        for (int s = 0; s < 4; s++) {
                            bool up = (((s*32 + lane) & k) == 0);
                            float o = __shfl_xor_sync(FULL, v[s], j);
                            bool lower = ((lane & j) == 0);
                            v[s] = (up == lower) ? fminf(v[s], o) : fmaxf(v[s], o);
                        }
                    }
                }
                #pragma unroll
                for (int s = 0; s < 4; s++) suS[s*32 + lane] = v[s];
                __syncwarp();
                float w0 = suS[lane*4+0], w1 = suS[lane*4+1], w2 = suS[lane*4+2], w3 = suS[lane*4+3];
                float pl = w0*w1*w2*w3;
                float incl = pl;
                #pragma unroll
                for (int off = 1; off < 32; off <<= 1) {
                    float tv = __shfl_up_sync(FULL, incl, off);
                    if (lane >= off) incl *= tv;
                }
                float base = __shfl_up_sync(FULL, incl, 1);
                if (lane == 0) base = 1.f;
                float run = base;
                aAl[lane*4+0] = (1.f - w0)*run; run *= w0;
                aAl[lane*4+1] = (1.f - w1)*run; run *= w1;
                aAl[lane*4+2] = (1.f - w2)*run; run *= w2;
                aAl[lane*4+3] = (1.f - w3)*run;
            } else if (wid >= 8 && wid < 12) {
                int n = tid - 256;
                const float4* m4 = (const float4*)(memS + n*64);
                const float4* k4p = (const float4*)wkS;
                float d = 0.f;
                #pragma unroll
                for (int q = 0; q < 16; q++) {
                    float4 mv = m4[q], kv = k4p[q];
                    d += mv.x*kv.x + mv.y*kv.y + mv.z*kv.z + mv.w*kv.w;
                }
                cwS[n] = d / ((normM[n] + 1e-6f) * scal[0]) * scal[1];
            }
            __syncthreads();

            if (wid == 0) {
                float c0 = cwS[lane*4+0], c1 = cwS[lane*4+1], c2 = cwS[lane*4+2], c3 = cwS[lane*4+3];
                float mx = fmaxf(fmaxf(c0,c1), fmaxf(c2,c3));
                #pragma unroll
                for (int o = 16; o; o >>= 1) mx = fmaxf(mx, __shfl_xor_sync(FULL, mx, o));
                float e0 = expf(c0-mx), e1 = expf(c1-mx), e2 = expf(c2-mx), e3 = expf(c3-mx);
                float sme = e0+e1+e2+e3;
                #pragma unroll
                for (int o = 16; o; o >>= 1) sme += __shfl_xor_sync(FULL, sme, o);
                float inv = 1.f/sme;
                float ag = scal[2], wg = scal[3];
                float ww0 = wg*(ag*aAl[lane*4+0] + (1.f-ag)*e0*inv);
                float ww1 = wg*(ag*aAl[lane*4+1] + (1.f-ag)*e1*inv);
                float ww2 = wg*(ag*aAl[lane*4+2] + (1.f-ag)*e2*inv);
                float ww3 = wg*(ag*aAl[lane*4+3] + (1.f-ag)*e3*inv);
                wwPer[lane*4+0]=ww0; wwPer[lane*4+1]=ww1; wwPer[lane*4+2]=ww2; wwPer[lane*4+3]=ww3;
                float S = ww0+ww1+ww2+ww3;
                #pragma unroll
                for (int o = 16; o; o >>= 1) S += __shfl_xor_sync(FULL, S, o);
                float oms = 1.f - S;
                pPer[lane*4+0] = oms*pPer[lane*4+0] + ww0;
                pPer[lane*4+1] = oms*pPer[lane*4+1] + ww1;
                pPer[lane*4+2] = oms*pPer[lane*4+2] + ww2;
                pPer[lane*4+3] = oms*pPer[lane*4+3] + ww3;
            }
            __syncthreads();

            {
                int n = n4, q = r4;
                float wwn = wwPer[n];
                float4* m4 = (float4*)(memS + n*64 + q*16);
                const float4* wv4 = (const float4*)(wvS + q*16);
                const float4* er4 = (const float4*)(erS + q*16);
                float ss = 0.f;
                #pragma unroll
                for (int i = 0; i < 4; i++) {
                    float4 m = m4[i], wv = wv4[i], er = er4[i];
                    m.x += wwn*(wv.x - er.x); m.y += wwn*(wv.y - er.y);
                    m.z += wwn*(wv.z - er.z); m.w += wwn*(wv.w - er.w);
                    m4[i] = m;
                    ss += m.x*m.x + m.y*m.y + m.z*m.z + m.w*m.w;
                }
                normP[n*4 + q] = ss;
            }
            __syncthreads();

            {
                int n = n4, r = r4;
                float ssn = normP[n*4+0] + normP[n*4+1] + normP[n*4+2] + normP[n*4+3];
                float nrm = sqrtf(ssn);
                const float4* m4 = (const float4*)(memS + n*64);
                const float4* rk4 = (const float4*)(rkS + r*64);
                float c = 0.f;
                #pragma unroll
                for (int q = 0; q < 16; q++) {
                    float4 mv = m4[q], kv = rk4[q];
                    c += mv.x*kv.x + mv.y*kv.y + mv.z*kv.z + mv.w*kv.w;
                }
                crS[n*4+r] = c / (nrm + 1e-6f) / rknS[r] * rsS[r];
                if (r == 0) normM[n] = nrm;
            }
            __syncthreads();

            // P5: links update + bwd partials + fwd walk (fused)
            {
                float rj[4][4], pj[4], wwj[4], bw[4][4];
                #pragma unroll
                for (int q = 0; q < 4; q++) {
                    pj[q] = pPer[lane+32*q]; wwj[q] = wwPer[lane+32*q];
                    #pragma unroll
                    for (int r = 0; r < 4; r++) { rj[r][q] = rwoldT[r*128 + lane + 32*q]; bw[q][r] = 0.f; }
                }
                int i0 = wid * 8;
                for (int ii = 0; ii < 8; ii++) {
                    int i = i0 + ii;
                    float wi = wwPer[i];
                    float ri0 = rwoldN[i*4+0], ri1 = rwoldN[i*4+1], ri2 = rwoldN[i*4+2], ri3 = rwoldN[i*4+3];
                    float f0 = 0.f, f1 = 0.f, f2 = 0.f, f3 = 0.f;
                    #pragma unroll
                    for (int q = 0; q < 4; q++) {
                        int j = lane + 32*q;
                        float L = linkS[i*LNK + j];
                        L = (1.f - wi - wwj[q])*L + wi*pj[q];
                        if (i == j) L = 0.f;
                        linkS[i*LNK + j] = L;
                        bw[q][0] = fmaf(L, ri0, bw[q][0]);
                        bw[q][1] = fmaf(L, ri1, bw[q][1]);
                        bw[q][2] = fmaf(L, ri2, bw[q][2]);
                        bw[q][3] = fmaf(L, ri3, bw[q][3]);
                        f0 = fmaf(L, rj[0][q], f0);
                        f1 = fmaf(L, rj[1][q], f1);
                        f2 = fmaf(L, rj[2][q], f2);
                        f3 = fmaf(L, rj[3][q], f3);
                    }
                    #pragma unroll
                    for (int o = 16; o; o >>= 1) {
                        f0 += __shfl_xor_sync(FULL, f0, o);
                        f1 += __shfl_xor_sync(FULL, f1, o);
                        f2 += __shfl_xor_sync(FULL, f2, o);
                        f3 += __shfl_xor_sync(FULL, f3, o);
                    }
                    if (lane == 0) {
                        fwdS[i*4+0] = f0; fwdS[i*4+1] = f1;
                        fwdS[i*4+2] = f2; fwdS[i*4+3] = f3;
                    }
                }
                #pragma unroll
                for (int q = 0; q < 4; q++)
                    #pragma unroll
                    for (int r = 0; r < 4; r++)
                        bwdP[wid*512 + (lane+32*q)*4 + r] = bw[q][r];
            }
            __syncthreads();

            if (wid < 4) {
                int r = wid;
                float m = -1e30f;
                #pragma unroll
                for (int q = 0; q < 4; q++) m = fmaxf(m, crS[(lane + 32*q)*4 + r]);
                #pragma unroll
                for (int o = 16; o; o >>= 1) m = fmaxf(m, __shfl_xor_sync(FULL, m, o));
                float s_ = 0.f;
                #pragma unroll
                for (int q = 0; q < 4; q++) s_ += expf(crS[(lane + 32*q)*4 + r] - m);
                #pragma unroll
                for (int o = 16; o; o >>= 1) s_ += __shfl_xor_sync(FULL, s_, o);
                if (lane == 0) { red[r*2] = m; red[r*2+1] = s_; }
            } else if (wid < 8) {
                int t2 = (wid - 4)*32 + lane;
                #pragma unroll
                for (int q = 0; q < 4; q++) {
                    int jr = t2 + 128*q;
                    float acc2 = 0.f;
                    #pragma unroll
                    for (int w16 = 0; w16 < 16; w16++) acc2 += bwdP[w16*512 + jr];
                    bwdS[jr] = acc2;
                }
            }
            __syncthreads();

            if (tid < 128) {
                int n = tid;
                #pragma unroll
                for (int r = 0; r < 4; r++) {
                    float c = expf(crS[n*4+r] - red[r*2]) / red[r*2+1];
                    float v = rmS[r*3+0]*bwdS[n*4+r] + rmS[r*3+1]*c + rmS[r*3+2]*fwdS[n*4+r];
                    rwnewS[n*4+r] = v;
                }
            }
            __syncthreads();

            if (tid < 256) {
                int w = tid >> 2, r = tid & 3;
                float acc2 = 0.f;
                #pragma unroll 8
                for (int n = 0; n < 128; n++) acc2 = fmaf(memS[n*64+w], rwnewS[n*4+r], acc2);
                g_r[b*256 + w*4 + r] = acc2;
                out[((size_t)t*B_ + b)*HR + 512 + w*4 + r] = acc2;
            }
            rwoldN[tid] = rwnewS[tid];
            rwoldT[(tid & 3)*128 + (tid >> 2)] = rwnewS[tid];
        }
        gbar(tgt);   // barC: g_r visible for next gates
    }

    if (tid < 384) {
        int idx = bid*384 + tid;
        out[(size_t)T_*B_*HR + idx] = __ldcg(out + (size_t)(T_-1)*B_*HR + idx);
    }
}

extern "C" void kernel_launch(void* const* d_in, const int* in_sizes, int n_in,
                              void* d_out, int out_size) {
    const float* x    = (const float*)d_in[0];
    const float* M0   = (const float*)d_in[1];
    const float* W_ih = (const float*)d_in[2];
    const float* b_ih = (const float*)d_in[3];
    const float* W_hh = (const float*)d_in[4];
    const float* b_hh = (const float*)d_in[5];
    const float* Wrk  = (const float*)d_in[6];
    const float* brk  = (const float*)d_in[7];
    const float* Wrs  = (const float*)d_in[8];
    const float* brs  = (const float*)d_in[9];
    const float* Wwk  = (const float*)d_in[10];
    const float* bwk  = (const float*)d_in[11];
    const float* Wws  = (const float*)d_in[12];
    const float* bws  = (const float*)d_in[13];
    const float* We   = (const float*)d_in[14];
    const float* be   = (const float*)d_in[15];
    const float* Wv   = (const float*)d_in[16];
    const float* bv   = (const float*)d_in[17];
    const float* Wfg  = (const float*)d_in[18];
    const float* bfg  = (const float*)d_in[19];
    const float* Wag  = (const float*)d_in[20];
    const float* bag  = (const float*)d_in[21];
    const float* Wwg  = (const float*)d_in[22];
    const float* bwg  = (const float*)d_in[23];
    const float* Wrm  = (const float*)d_in[24];
    const float* brm  = (const float*)d_in[25];
    float* out = (float*)d_out;

    cudaFuncSetAttribute(k_dnc, cudaFuncAttributeMaxDynamicSharedMemorySize, SM_BYTES);

    k_init<<<128, 256>>>();
    k_dnc<<<GRID_, TPB_, SM_BYTES>>>(x, M0, W_ih, b_ih, W_hh, b_hh,
        Wrk, brk, Wrs, brs, Wwk, bwk, Wws, bws, We, be, Wv, bv,
        Wfg, bfg, Wag, bag, Wwg, bwg, Wrm, brm, out);
}